// round 15
// baseline (speedup 1.0000x reference)
#include <cuda_runtime.h>

// DTW loss: 32 independent 1024x1024 wavefront DPs, fused with path-loss
// accumulation (W[i,j] = w(i,j) + W[argmin-pred]) -> no backtrack needed.
//
// R14 = R13 with the preprocessor fix (ESTEP indirection so the A_SET/B_SET
// register lists expand BEFORE STEP's arguments are counted).
// One warp per SMSP: 4 warps x RR=8 rows/thread (BAND=256), branch-free
// role-swap body (zero data-movement MOVs), carried [R+imm] addressing,
// packed f32x2 distance, unconditional publish.

#define NN 1024
#define MM 1024
#define TT 128               // threads per block
#define NWARP 4
#define BAND 256             // rows per warp stage (8 rows/thread)
#define RING 2048
#define SCH 8                // diagonals per sync chunk = one window rotation

#define FINF (__int_as_float(0x7f800000))
#define SENT 1.0e18f

__device__ float g_partial[64];

static __forceinline__ __device__ float fsqrt_approx(float x) {
    float r;
    asm("sqrt.approx.f32 %0, %1;" : "=f"(r) : "f"(x));
    return r;
}
static __forceinline__ __device__ unsigned smem_u32(const void* p) {
    return (unsigned)__cvta_generic_to_shared(p);
}

// packed negated-target array: logical j in [-PADF, ...], idx = u + u/4
#define PADF 263             // 263 % 4 == 3 -> swizzle-walk phase 3 at S=0
#define STCNT 1544           // u in [0, 1543]
#define STN2 1984
#define NRING 4              // slots 0..2 producers, slot 3 = FINF dummy
#define SMEM_BYTES (NRING * RING * 8 + STN2 * 8 + 32 + 64)

__global__ void __launch_bounds__(TT, 1)
dtw_forward_kernel(const float* __restrict__ preds,
                   const float* __restrict__ targs,
                   const float* __restrict__ subcoef)
{
    extern __shared__ unsigned char smem_raw[];
    float2*   ring = (float2*)smem_raw;               // [NRING][RING]
    float2*   sT   = (float2*)(ring + NRING * RING);  // negated + swizzled
    unsigned* cnt  = (unsigned*)(sT + STN2);          // [4] progress counters
    const unsigned dummyB = smem_u32(cnt + 8);        // 64B dummy publish

    const int b    = blockIdx.x;
    const int tid  = threadIdx.x;
    const int lane = tid & 31;
    const int warp = tid >> 5;

    const float* __restrict__ pb = preds + (size_t)b * NN * 4;
    const float* __restrict__ tb = targs + (size_t)b * MM * 4;

    // stage NEGATED targets with sentinel pad
    for (int u = tid; u < STCNT; u += TT) {
        int j = u - PADF;
        int idx = u + (u >> 2);
        bool in = (unsigned)j < (unsigned)MM;
        int jc = in ? j : 0;
        sT[idx] = in ? make_float2(-tb[jc * 4 + 0], -tb[jc * 4 + 1])
                     : make_float2(-SENT, -SENT);
    }
    // prefill warp0's dummy ring slot with {FINF, 0}
    for (int u = tid; u < RING; u += TT)
        ring[3 * RING + u] = make_float2(FINF, 0.f);
    if (tid < NWARP) cnt[tid] = 0;

    const float s0 = subcoef[0];
    const float s1 = subcoef[1];

    const int i0 = tid * 8;            // first owned row
    unsigned long long P0, P1, P2, P3, P4, P5, P6, P7;
#define LOADP(PN, R) do { float x_ = pb[(i0 + (R)) * 4 + 0];                 \
    float y_ = pb[(i0 + (R)) * 4 + 1];                                       \
    asm("mov.b64 %0, {%1, %2};" : "=l"(PN) : "f"(x_), "f"(y_)); } while (0)
    LOADP(P0, 0); LOADP(P1, 1); LOADP(P2, 2); LOADP(P3, 3);
    LOADP(P4, 4); LOADP(P5, 5); LOADP(P6, 6); LOADP(P7, 7);
#undef LOADP

    // role-alternating diag sets
    float Da0=FINF,Da1=FINF,Da2=FINF,Da3=FINF,Da4=FINF,Da5=FINF,Da6=FINF,Da7=FINF;
    float Db0=FINF,Db1=FINF,Db2=FINF,Db3=FINF,Db4=FINF,Db5=FINF,Db6=FINF,Db7=FINF;
    float Wa0=0,Wa1=0,Wa2=0,Wa3=0,Wa4=0,Wa5=0,Wa6=0,Wa7=0;
    float Wb0=0,Wb1=0,Wb2=0,Wb3=0,Wb4=0,Wb5=0,Wb6=0,Wb7=0;
    float pDa = (warp == 0 && lane == 0) ? 0.f : FINF;
    float pWa = 0.f;
    float pDb = FINF, pWb = 0.f;

    const bool     lane0   = (lane == 0);
    const bool     ringOn  = (warp != 0);
    const unsigned pubFlag = (warp < NWARP - 1 && lane == 31) ? 1u : 0u;
    const unsigned myCnt   = smem_u32(&cnt[warp]);
    const unsigned prevCnt = smem_u32(&cnt[warp > 0 ? warp - 1 : 0]);
    const float2*  srcRing = ringOn ? &ring[(warp - 1) * RING]
                                    : &ring[3 * RING + 1];

    const int kstart = warp * BAND;

    // carried chunk-base addresses (hot loop uses [R+imm])
    unsigned srcB = smem_u32(srcRing + kstart) - 8u;             // ring[k-1]
    unsigned pubB = pubFlag ? (smem_u32(&ring[warp * RING]) + (unsigned)kstart * 8u)
                            : dummyB;
    const unsigned incB = pubFlag ? 64u : 0u;
    unsigned tB;
    {
        const int u0 = kstart + PADF - i0;        // u0 % 4 == 3 for all tids
        tB = smem_u32(sT) + (unsigned)(u0 + (u0 >> 2)) * 8u;
    }

    __syncthreads();

    // chunk-0 poll (uniform) + peel of srcRing[kstart-2] for pDa
    if (ringOn) {
        const int need = kstart + SCH - 1;
        unsigned c;
        asm volatile("ld.acquire.cta.shared.u32 %0, [%1];" : "=r"(c) : "r"(prevCnt));
        while ((int)c < need) {
            __nanosleep(32);
            asm volatile("ld.acquire.cta.shared.u32 %0, [%1];" : "=r"(c) : "r"(prevCnt));
        }
        if (lane0) {
            float2 e = srcRing[kstart - 2];
            pDa = e.x; pWa = e.y;
        }
    }

    // cyclic target window prefetch: q_r = sT[u0 - r], r = 1..7; q0 dead
    unsigned long long q0, q1, q2, q3, q4, q5, q6, q7;
    {
        const unsigned long long* sTu = (const unsigned long long*)sT;
        const int u0 = kstart + PADF - i0;
        int u;
        u = u0 - 1; q1 = sTu[u + (u >> 2)];
        u = u0 - 2; q2 = sTu[u + (u >> 2)];
        u = u0 - 3; q3 = sTu[u + (u >> 2)];
        u = u0 - 4; q4 = sTu[u + (u >> 2)];
        u = u0 - 5; q5 = sTu[u + (u >> 2)];
        u = u0 - 6; q6 = sTu[u + (u >> 2)];
        u = u0 - 7; q7 = sTu[u + (u >> 2)];
        q0 = q1;
    }

    // ---- one cell: first-min-wins argmin over [diag, up, left] -----------
#define CELL(PP, TQ, UP, DG, WU, WD, LF, WL, OD, OW) do {                    \
    unsigned long long dxy_;                                                 \
    asm("add.rn.f32x2 %0, %1, %2;" : "=l"(dxy_) : "l"(PP), "l"(TQ));         \
    float dx_, dy_;                                                          \
    asm("mov.b64 {%0, %1}, %2;" : "=f"(dx_), "=f"(dy_) : "l"(dxy_));         \
    const float c_ = fsqrt_approx(fmaf(dy_, dy_, dx_ * dx_));                \
    const float w_ = fmaf(fabsf(dy_), s1, fabsf(dx_) * s0);                  \
    const float m1 = fminf((UP), (LF));                                      \
    float ws = ((UP) <= (LF)) ? (WU) : (WL);                                 \
    ws = ((DG) <= m1) ? (WD) : ws;                                           \
    OD = c_ + fminf((DG), m1);                                               \
    OW = w_ + ws;                                                            \
} while (0)

    // ---- one step; outputs written INTO the "prev" register set ----------
#define STEP(S, RINGF, TOFF,                                                 \
             DC0,DC1,DC2,DC3,DC4,DC5,DC6,DC7, WC0,WC1,WC2,WC3,WC4,WC5,WC6,WC7,\
             DP0,DP1,DP2,DP3,DP4,DP5,DP6,DP7, WP0,WP1,WP2,WP3,WP4,WP5,WP6,WP7,\
             PCD, PCW, PND, PNW, QL, QA, QB, QC, QD, QE, QF, QG) do {        \
    float nD1 = __shfl_up_sync(0xffffffffu, DC7, 1);                         \
    float nW1 = __shfl_up_sync(0xffffffffu, WC7, 1);                         \
    if (RINGF) {                                                             \
        float rD_, rW_;                                                      \
        asm("ld.shared.v2.f32 {%0, %1}, [%2+%3];"                            \
            : "=f"(rD_), "=f"(rW_) : "r"(srcB), "n"((S) * 8));               \
        nD1 = lane0 ? rD_ : nD1;                                             \
        nW1 = lane0 ? rW_ : nW1;                                             \
    } else {                                                                 \
        nD1 = lane0 ? FINF : nD1;                                            \
        nW1 = lane0 ? 0.f  : nW1;                                            \
    }                                                                        \
    PND = nD1; PNW = nW1;                                                    \
    asm("ld.shared.b64 %0, [%1+%2];" : "=l"(QL) : "r"(tB), "n"(TOFF));       \
    CELL(P7, QG, DC6, DP6, WC6, WP6, DC7, WC7, DP7, WP7);                    \
    CELL(P6, QF, DC5, DP5, WC5, WP5, DC6, WC6, DP6, WP6);                    \
    CELL(P5, QE, DC4, DP4, WC4, WP4, DC5, WC5, DP5, WP5);                    \
    CELL(P4, QD, DC3, DP3, WC3, WP3, DC4, WC4, DP4, WP4);                    \
    CELL(P3, QC, DC2, DP2, WC2, WP2, DC3, WC3, DP3, WP3);                    \
    CELL(P2, QB, DC1, DP1, WC1, WP1, DC2, WC2, DP2, WP2);                    \
    CELL(P1, QA, DC0, DP0, WC0, WP0, DC1, WC1, DP1, WP1);                    \
    CELL(P0, QL, nD1, PCD, nW1, PCW, DC0, WC0, DP0, WP0);                    \
    asm volatile("st.shared.v2.f32 [%0+%1], {%2, %3};"                       \
                 :: "r"(pubB), "n"((S) * 8), "f"(DP7), "f"(WP7) : "memory"); \
} while (0)

    // indirection: variadic args are macro-expanded BEFORE substitution,
    // so A_SET/B_SET flatten into 16 registers each before STEP is counted
#define ESTEP(...) STEP(__VA_ARGS__)

#define A_SET Da0,Da1,Da2,Da3,Da4,Da5,Da6,Da7, Wa0,Wa1,Wa2,Wa3,Wa4,Wa5,Wa6,Wa7
#define B_SET Db0,Db1,Db2,Db3,Db4,Db5,Db6,Db7, Wb0,Wb1,Wb2,Wb3,Wb4,Wb5,Wb6,Wb7

    // 8 steps = one full window rotation (period 8), role parity period 2.
    // target offsets {0,16,24,32,40,56,64,72}: swizzle walk, phase 3 start.
#define CHUNK8(RINGF) do {                                                   \
    ESTEP(0, RINGF, 0,  A_SET, B_SET, pDa,pWa,pDb,pWb, q0,q1,q2,q3,q4,q5,q6,q7);\
    ESTEP(1, RINGF, 16, B_SET, A_SET, pDb,pWb,pDa,pWa, q7,q0,q1,q2,q3,q4,q5,q6);\
    ESTEP(2, RINGF, 24, A_SET, B_SET, pDa,pWa,pDb,pWb, q6,q7,q0,q1,q2,q3,q4,q5);\
    ESTEP(3, RINGF, 32, B_SET, A_SET, pDb,pWb,pDa,pWa, q5,q6,q7,q0,q1,q2,q3,q4);\
    ESTEP(4, RINGF, 40, A_SET, B_SET, pDa,pWa,pDb,pWb, q4,q5,q6,q7,q0,q1,q2,q3);\
    ESTEP(5, RINGF, 56, B_SET, A_SET, pDb,pWb,pDa,pWa, q3,q4,q5,q6,q7,q0,q1,q2);\
    ESTEP(6, RINGF, 64, A_SET, B_SET, pDa,pWa,pDb,pWb, q2,q3,q4,q5,q6,q7,q0,q1);\
    ESTEP(7, RINGF, 72, B_SET, A_SET, pDb,pWb,pDa,pWa, q1,q2,q3,q4,q5,q6,q7,q0);\
} while (0)

#define DTW_RELEASE(VAL) do {                                                \
    asm volatile("{\n\t.reg .pred p;\n\tsetp.ne.u32 p, %0, 0;\n\t"           \
                 "@p st.release.cta.shared.u32 [%1], %2;\n\t}"               \
                 :: "r"(pubFlag), "r"(myCnt), "r"((unsigned)(VAL))           \
                 : "memory");                                                \
} while (0)
    // ----------------------------------------------------------------------

    int kb = kstart;

    // Phase A: 128 chunks x 8 steps, ring-fed (k in [kstart, kstart+1024))
    for (int c = 0; c < MM / SCH; ++c) {
        if (ringOn & (c != 0)) {                      // uniform poll per chunk
            const int need = kb + SCH - 1;
            unsigned cv;
            asm volatile("ld.acquire.cta.shared.u32 %0, [%1];" : "=r"(cv) : "r"(prevCnt));
            while ((int)cv < need) {
                __nanosleep(32);
                asm volatile("ld.acquire.cta.shared.u32 %0, [%1];" : "=r"(cv) : "r"(prevCnt));
            }
        }
        CHUNK8(true);
        kb += SCH;
        DTW_RELEASE(kb);
        srcB += SCH * 8;
        pubB += incB;
        tB   += 80;
    }

    // Phase B: 32 chunks x 8 steps, lane0 neighbor statically FINF.
    // 255 real steps + 1 dummy (rel=1279, writes the "a" set / unread ring
    // index) -> result at rel=1278 is preserved in the "b" set.
    for (int c = 0; c < 32; ++c) {
        CHUNK8(false);
        kb += SCH;
        DTW_RELEASE(kb);
        pubB += incB;
        tB   += 80;
    }

    if (tid == TT - 1)                 // rel=1278 output: Wb7 == W[N-1][M-1]
        g_partial[b] = Wb7;
}

__global__ void dtw_reduce_kernel(float* __restrict__ out, int B)
{
    int l = threadIdx.x;
    float s = 0.f;
    if (l < B)      s += g_partial[l];
    if (l + 32 < B) s += g_partial[l + 32];
#pragma unroll
    for (int o = 16; o; o >>= 1) s += __shfl_xor_sync(0xffffffffu, s, o);
    if (l == 0) out[0] = s;
}

extern "C" void kernel_launch(void* const* d_in, const int* in_sizes, int n_in,
                              void* d_out, int out_size)
{
    const float* preds   = (const float*)d_in[0];
    const float* targs   = (const float*)d_in[1];
    const float* subcoef = (const float*)d_in[2];
    float* out = (float*)d_out;

    int B = in_sizes[0] / (NN * 4);
    if (B < 1) B = 1;
    if (B > 64) B = 64;

    cudaFuncSetAttribute(dtw_forward_kernel,
                         cudaFuncAttributeMaxDynamicSharedMemorySize, SMEM_BYTES);

    dtw_forward_kernel<<<B, TT, SMEM_BYTES>>>(preds, targs, subcoef);
    dtw_reduce_kernel<<<1, 32>>>(out, B);
}

// round 16
// speedup vs baseline: 1.5392x; 1.5392x over previous
#include <cuda_runtime.h>

// DTW loss: 32 independent 1024x1024 wavefront DPs, fused with path-loss
// accumulation (W[i,j] = w(i,j) + W[argmin-pred]) -> no backtrack needed.
//
// R15 = R12 (best: 170.5us; 8 warps x RR=4, 2 warps/SMSP, branch-free
// role-swap body, carried [R+imm] addressing, packed f32x2 distance,
// unconditional publish, SCH=8) + the final reduction FUSED into the
// forward kernel via an arrival counter (last CTA warp-reduces g_partial
// and writes out). One launch per call -> ncu -s5 now lands on the
// forward kernel, and the ~4us reduce launch disappears.

#define NN 1024
#define MM 1024
#define TT 256               // threads per block
#define NWARP 8
#define BAND 128             // rows per warp stage (4 rows/thread)
#define RING 2048
#define SCH 8                // diagonals per sync chunk

#define FINF (__int_as_float(0x7f800000))
#define SENT 1.0e18f

__device__ float g_partial[64];
__device__ unsigned g_arrive = 0;

static __forceinline__ __device__ float fsqrt_approx(float x) {
    float r;
    asm("sqrt.approx.f32 %0, %1;" : "=f"(r) : "f"(x));
    return r;
}
static __forceinline__ __device__ unsigned smem_u32(const void* p) {
    return (unsigned)__cvta_generic_to_shared(p);
}

// packed negated-target array: logical j in [-PADF, ...], idx = u + u/4
#define PADF 127
#define STN2 1600
#define NRING 8              // slots 0..6 producers, slot 7 = FINF dummy
#define SMEM_BYTES (NRING * RING * 8 + STN2 * 8 + 32 + 64)

__global__ void __launch_bounds__(TT, 1)
dtw_forward_kernel(const float* __restrict__ preds,
                   const float* __restrict__ targs,
                   const float* __restrict__ subcoef,
                   float* __restrict__ out)
{
    extern __shared__ unsigned char smem_raw[];
    float2*   ring = (float2*)smem_raw;               // [NRING][RING]
    float2*   sT   = (float2*)(ring + NRING * RING);  // negated + swizzled
    unsigned* cnt  = (unsigned*)(sT + STN2);          // [8] progress counters
    const unsigned dummyB = smem_u32(cnt + 8);        // 64B dummy publish
    __shared__ unsigned sIsLast;

    const int b    = blockIdx.x;
    const int tid  = threadIdx.x;
    const int lane = tid & 31;
    const int warp = tid >> 5;

    const float* __restrict__ pb = preds + (size_t)b * NN * 4;
    const float* __restrict__ tb = targs + (size_t)b * MM * 4;

    // stage NEGATED targets with sentinel pad
    for (int u = tid; u < PADF + MM + BAND + 1; u += TT) {
        int j = u - PADF;
        int idx = u + (u >> 2);
        bool in = (unsigned)j < (unsigned)MM;
        int jc = in ? j : 0;
        sT[idx] = in ? make_float2(-tb[jc * 4 + 0], -tb[jc * 4 + 1])
                     : make_float2(-SENT, -SENT);
    }
    // prefill warp0's dummy ring slot with {FINF, 0}
    for (int u = tid; u < RING; u += TT)
        ring[7 * RING + u] = make_float2(FINF, 0.f);
    if (tid < NWARP) cnt[tid] = 0;

    const float s0 = subcoef[0];
    const float s1 = subcoef[1];

    const int i0 = tid * 4;            // first owned row
    unsigned long long P0, P1, P2, P3; // packed (px, py) per owned row
    {
        float x, y;
        x = pb[(i0 + 0) * 4 + 0]; y = pb[(i0 + 0) * 4 + 1];
        asm("mov.b64 %0, {%1, %2};" : "=l"(P0) : "f"(x), "f"(y));
        x = pb[(i0 + 1) * 4 + 0]; y = pb[(i0 + 1) * 4 + 1];
        asm("mov.b64 %0, {%1, %2};" : "=l"(P1) : "f"(x), "f"(y));
        x = pb[(i0 + 2) * 4 + 0]; y = pb[(i0 + 2) * 4 + 1];
        asm("mov.b64 %0, {%1, %2};" : "=l"(P2) : "f"(x), "f"(y));
        x = pb[(i0 + 3) * 4 + 0]; y = pb[(i0 + 3) * 4 + 1];
        asm("mov.b64 %0, {%1, %2};" : "=l"(P3) : "f"(x), "f"(y));
    }

    // role-alternating diag sets: "a" = diag k-1, "b" = diag k-2 at even rel
    float Da0 = FINF, Da1 = FINF, Da2 = FINF, Da3 = FINF;
    float Db0 = FINF, Db1 = FINF, Db2 = FINF, Db3 = FINF;
    float Wa0 = 0.f,  Wa1 = 0.f,  Wa2 = 0.f,  Wa3 = 0.f;
    float Wb0 = 0.f,  Wb1 = 0.f,  Wb2 = 0.f,  Wb3 = 0.f;
    float pDa = (warp == 0 && lane == 0) ? 0.f : FINF;
    float pWa = 0.f;
    float pDb = FINF, pWb = 0.f;

    const bool     lane0   = (lane == 0);
    const bool     ringOn  = (warp != 0);
    const unsigned pubFlag = (warp < NWARP - 1 && lane == 31) ? 1u : 0u;
    const unsigned myCnt   = smem_u32(&cnt[warp]);
    const unsigned prevCnt = smem_u32(&cnt[warp > 0 ? warp - 1 : 0]);
    const float2*  srcRing = ringOn ? &ring[(warp - 1) * RING]
                                    : &ring[7 * RING + 1];

    const int kstart = warp * BAND;

    // carried addresses (chunk bases; hot loop uses [R+imm])
    unsigned srcB = smem_u32(srcRing + kstart) - 8u;             // ring[k-1]
    unsigned pubB = pubFlag ? (smem_u32(&ring[warp * RING]) + (unsigned)kstart * 8u)
                            : dummyB;
    const unsigned incB = pubFlag ? 64u : 0u;
    unsigned tB;
    {
        const int u0 = kstart + PADF - i0;        // in [3, 127]
        tB = smem_u32(sT) + (unsigned)(u0 + (u0 >> 2)) * 8u;
    }

    __syncthreads();

    // chunk-0 poll (uniform) + peel of srcRing[kstart-2] for pDa
    if (ringOn) {
        const int need = kstart + SCH - 1;
        unsigned c;
        asm volatile("ld.acquire.cta.shared.u32 %0, [%1];" : "=r"(c) : "r"(prevCnt));
        while ((int)c < need) {
            __nanosleep(32);
            asm volatile("ld.acquire.cta.shared.u32 %0, [%1];" : "=r"(c) : "r"(prevCnt));
        }
        if (lane0) {
            float2 e = srcRing[kstart - 2];
            pDa = e.x; pWa = e.y;
        }
    }

    // cyclic target window prefetch: q1=sT[u0-1], q2=sT[u0-2], q3=sT[u0-3]
    unsigned long long q0, q1, q2, q3;
    {
        const unsigned long long* sTu = (const unsigned long long*)sT;
        const int u0 = kstart + PADF - i0;
        int u;
        u = u0 - 1; q1 = sTu[u + (u >> 2)];
        u = u0 - 2; q2 = sTu[u + (u >> 2)];
        u = u0 - 3; q3 = sTu[u + (u >> 2)];
        q0 = q1;   // dead; overwritten by first step
    }

    // ---- one cell: first-min-wins argmin over [diag, up, left] -----------
#define CELL(PP, TQ, UP, DG, WU, WD, LF, WL, OD, OW) do {                    \
    unsigned long long dxy_;                                                 \
    asm("add.rn.f32x2 %0, %1, %2;" : "=l"(dxy_) : "l"(PP), "l"(TQ));         \
    float dx_, dy_;                                                          \
    asm("mov.b64 {%0, %1}, %2;" : "=f"(dx_), "=f"(dy_) : "l"(dxy_));         \
    const float c_ = fsqrt_approx(fmaf(dy_, dy_, dx_ * dx_));                \
    const float w_ = fmaf(fabsf(dy_), s1, fabsf(dx_) * s0);                  \
    const float m1 = fminf((UP), (LF));                                      \
    float ws = ((UP) <= (LF)) ? (WU) : (WL);                                 \
    ws = ((DG) <= m1) ? (WD) : ws;                                           \
    OD = c_ + fminf((DG), m1);                                               \
    OW = w_ + ws;                                                            \
} while (0)

    // ---- one step; outputs written INTO the "prev" register set ----------
#define STEP(S, RINGF, TOFF,                                                 \
             DC0, DC1, DC2, DC3, WC0, WC1, WC2, WC3,                         \
             DP0, DP1, DP2, DP3, WP0, WP1, WP2, WP3,                         \
             PCD, PCW, PND, PNW, QL, QA, QB, QC) do {                        \
    float nD1 = __shfl_up_sync(0xffffffffu, DC3, 1);                         \
    float nW1 = __shfl_up_sync(0xffffffffu, WC3, 1);                         \
    if (RINGF) {                                                             \
        float rD_, rW_;                                                      \
        asm("ld.shared.v2.f32 {%0, %1}, [%2+%3];"                            \
            : "=f"(rD_), "=f"(rW_) : "r"(srcB), "n"((S) * 8));               \
        nD1 = lane0 ? rD_ : nD1;                                             \
        nW1 = lane0 ? rW_ : nW1;                                             \
    } else {                                                                 \
        nD1 = lane0 ? FINF : nD1;                                            \
        nW1 = lane0 ? 0.f  : nW1;                                            \
    }                                                                        \
    PND = nD1; PNW = nW1;                                                    \
    asm("ld.shared.b64 %0, [%1+%2];" : "=l"(QL) : "r"(tB), "n"(TOFF));       \
    CELL(P3, QC, DC2, DP2, WC2, WP2, DC3, WC3, DP3, WP3);                    \
    CELL(P2, QB, DC1, DP1, WC1, WP1, DC2, WC2, DP2, WP2);                    \
    CELL(P1, QA, DC0, DP0, WC0, WP0, DC1, WC1, DP1, WP1);                    \
    CELL(P0, QL, nD1, PCD, nW1, PCW, DC0, WC0, DP0, WP0);                    \
    asm volatile("st.shared.v2.f32 [%0+%1], {%2, %3};"                       \
                 :: "r"(pubB), "n"((S) * 8), "f"(DP3), "f"(WP3) : "memory"); \
} while (0)

    // 8 steps = 2 full role/window rotations; target offsets {0,16,24,32,
    // 40,56,64,72} encode the carried swizzle walk (u%4 phase = 3 at S=0)
#define CHUNK8(RINGF) do {                                                   \
    STEP(0, RINGF, 0,  Da0,Da1,Da2,Da3, Wa0,Wa1,Wa2,Wa3,                     \
         Db0,Db1,Db2,Db3, Wb0,Wb1,Wb2,Wb3, pDa,pWa,pDb,pWb, q0,q1,q2,q3);    \
    STEP(1, RINGF, 16, Db0,Db1,Db2,Db3, Wb0,Wb1,Wb2,Wb3,                     \
         Da0,Da1,Da2,Da3, Wa0,Wa1,Wa2,Wa3, pDb,pWb,pDa,pWa, q3,q0,q1,q2);    \
    STEP(2, RINGF, 24, Da0,Da1,Da2,Da3, Wa0,Wa1,Wa2,Wa3,                     \
         Db0,Db1,Db2,Db3, Wb0,Wb1,Wb2,Wb3, pDa,pWa,pDb,pWb, q2,q3,q0,q1);    \
    STEP(3, RINGF, 32, Db0,Db1,Db2,Db3, Wb0,Wb1,Wb2,Wb3,                     \
         Da0,Da1,Da2,Da3, Wa0,Wa1,Wa2,Wa3, pDb,pWb,pDa,pWa, q1,q2,q3,q0);    \
    STEP(4, RINGF, 40, Da0,Da1,Da2,Da3, Wa0,Wa1,Wa2,Wa3,                     \
         Db0,Db1,Db2,Db3, Wb0,Wb1,Wb2,Wb3, pDa,pWa,pDb,pWb, q0,q1,q2,q3);    \
    STEP(5, RINGF, 56, Db0,Db1,Db2,Db3, Wb0,Wb1,Wb2,Wb3,                     \
         Da0,Da1,Da2,Da3, Wa0,Wa1,Wa2,Wa3, pDb,pWb,pDa,pWa, q3,q0,q1,q2);    \
    STEP(6, RINGF, 64, Da0,Da1,Da2,Da3, Wa0,Wa1,Wa2,Wa3,                     \
         Db0,Db1,Db2,Db3, Wb0,Wb1,Wb2,Wb3, pDa,pWa,pDb,pWb, q2,q3,q0,q1);    \
    STEP(7, RINGF, 72, Db0,Db1,Db2,Db3, Wb0,Wb1,Wb2,Wb3,                     \
         Da0,Da1,Da2,Da3, Wa0,Wa1,Wa2,Wa3, pDb,pWb,pDa,pWa, q1,q2,q3,q0);    \
} while (0)

#define DTW_RELEASE(VAL) do {                                                \
    asm volatile("{\n\t.reg .pred p;\n\tsetp.ne.u32 p, %0, 0;\n\t"           \
                 "@p st.release.cta.shared.u32 [%1], %2;\n\t}"               \
                 :: "r"(pubFlag), "r"(myCnt), "r"((unsigned)(VAL))           \
                 : "memory");                                                \
} while (0)
    // ----------------------------------------------------------------------

    int kb = kstart;

    // Phase A: 128 chunks x 8 steps, ring-fed
    for (int c = 0; c < MM / SCH; ++c) {
        if (ringOn & (c != 0)) {                      // uniform poll per chunk
            const int need = kb + SCH - 1;
            unsigned cv;
            asm volatile("ld.acquire.cta.shared.u32 %0, [%1];" : "=r"(cv) : "r"(prevCnt));
            while ((int)cv < need) {
                __nanosleep(32);
                asm volatile("ld.acquire.cta.shared.u32 %0, [%1];" : "=r"(cv) : "r"(prevCnt));
            }
        }
        CHUNK8(true);
        kb += SCH;
        DTW_RELEASE(kb);
        srcB += SCH * 8;
        pubB += incB;
        tB   += 80;
    }

    // Phase B: 16 chunks x 8 steps, lane0 neighbor statically FINF.
    // 127 real steps + 1 dummy (rel=1151, outputs land in the "a" set /
    // unread ring index) -> result at rel=1150 is preserved in the "b" set.
    for (int c = 0; c < 16; ++c) {
        CHUNK8(false);
        kb += SCH;
        DTW_RELEASE(kb);
        pubB += incB;
        tB   += 80;
    }

    // ---- fused final reduction (arrival counter, last CTA reduces) -------
    __syncthreads();                   // all DP work in this CTA done
    if (tid == TT - 1) {               // rel=1150 output: Wb3 == W[N-1][M-1]
        g_partial[b] = Wb3;
        __threadfence();               // publish before arrival
        unsigned old = atomicAdd(&g_arrive, 1u);
        sIsLast = (old == (unsigned)(gridDim.x - 1)) ? 1u : 0u;
    }
    __syncthreads();
    if (sIsLast && warp == NWARP - 1) {
        __threadfence();               // order after all arrivals
        const int B = (int)gridDim.x;
        volatile float* gp = g_partial;
        float s = 0.f;
        if (lane < B)      s += gp[lane];
        if (lane + 32 < B) s += gp[lane + 32];
#pragma unroll
        for (int o = 16; o; o >>= 1) s += __shfl_xor_sync(0xffffffffu, s, o);
        if (lane == 0) {
            out[0] = s;
            g_arrive = 0;              // reset for next graph replay
        }
    }
}

extern "C" void kernel_launch(void* const* d_in, const int* in_sizes, int n_in,
                              void* d_out, int out_size)
{
    const float* preds   = (const float*)d_in[0];
    const float* targs   = (const float*)d_in[1];
    const float* subcoef = (const float*)d_in[2];
    float* out = (float*)d_out;

    int B = in_sizes[0] / (NN * 4);
    if (B < 1) B = 1;
    if (B > 64) B = 64;

    cudaFuncSetAttribute(dtw_forward_kernel,
                         cudaFuncAttributeMaxDynamicSharedMemorySize, SMEM_BYTES);

    dtw_forward_kernel<<<B, TT, SMEM_BYTES>>>(preds, targs, subcoef, out);
}